// round 15
// baseline (speedup 1.0000x reference)
#include <cuda_runtime.h>
#include <math.h>

// ChamferLoss_31044023616212: one-sided Chamfer distance
//   set1: [2, 8192, 3] f32, set2: [2, 8192, 3] f32 -> scalar f32
//
// R14 (resubmit; prior round was an infra failure): exact z-bucket pruning
// with WARP-PRIVATE windows and the packed FFMA2 broadcast micro-pattern.
//  * bucket kernel sorts both sets by z (512 bins); set2 is stored
//    PAIR-TRANSPOSED so the packed loop reads it directly; set1 keeps
//    its original index.
//  * search: warp = 32 consecutive sorted x (1 per lane).
//    phase A: warp scans +-1 bucket jointly -> per-lane upper bound ub.
//    phase B: window [warp_zmin - r, warp_zmax + r], r = warp-max ub,
//    provably contains every lane's true NN; warp scans it with uniform
//    (broadcast) LDG.128 pairs: 2 LDG + 3 FFMA2 + 2 MIN per candidate-pair
//    serving all 32 lanes.
//  * superset scans + fminf set-invariance + orig-index writes +
//    fixed-order final sum -> exact and deterministic.

#define NBATCH 2
#define NB     512
#define ZMIN   (-6.0f)
#define ZWID   (12.0f / NB)
#define ZINV   (NB / 12.0f)
#define NMAX   8192
#define TS     128                 // 4 warps per search block

__device__ float  g_ypk[NBATCH][NMAX * 4];  // pair-transposed sorted set2
__device__ int    g_yoff[NBATCH][NB + 1];   // set2 bucket offsets
__device__ float4 g_x[NBATCH][NMAX];        // sorted set1: (x,y,z,orig_idx)
__device__ float  g_dist[NBATCH * NMAX];    // per-point NN dist (orig order)
__device__ int    g_count = 0;

typedef unsigned long long u64;

__device__ __forceinline__ u64 ffma2(u64 a, u64 b, u64 c) {
    u64 d;
    asm("fma.rn.f32x2 %0, %1, %2, %3;" : "=l"(d) : "l"(a), "l"(b), "l"(c));
    return d;
}
__device__ __forceinline__ u64 bcast2(float x) {
    u64 r;
    asm("mov.b64 %0, {%1, %1};" : "=l"(r) : "f"(x));
    return r;
}
__device__ __forceinline__ void unpack2(u64 v, float& a, float& b) {
    asm("mov.b64 {%0, %1}, %2;" : "=f"(a), "=f"(b) : "l"(v));
}

// ---------------- kernel 1: bucket both sets by z ----------------
extern "C" __global__ void __launch_bounds__(1024, 1)
bucket_kernel(const float* __restrict__ set1,
              const float* __restrict__ set2, int n)
{
    __shared__ int hist[NB];
    __shared__ int offs[NB + 1];
    __shared__ int cur[NB];

    const int  job = blockIdx.x;        // 0,1: set2 b=0,1   2,3: set1 b=0,1
    const int  b   = job & 1;
    const bool isX = (job >> 1) != 0;
    const float* src = (isX ? set1 : set2) + (size_t)b * n * 3;
    const int tid = threadIdx.x;

    for (int i = tid; i < NB; i += 1024) hist[i] = 0;
    __syncthreads();

    for (int j = tid; j < n; j += 1024) {
        float z = src[3 * j + 2];
        int ib = min(max((int)((z - ZMIN) * ZINV), 0), NB - 1);
        atomicAdd(&hist[ib], 1);
    }
    __syncthreads();

    if (tid < NB) offs[tid + 1] = hist[tid];
    if (tid == 0) offs[0] = 0;
    __syncthreads();
    for (int s = 1; s < NB; s <<= 1) {
        int add = 0;
        if (tid < NB && tid >= s) add = offs[tid + 1 - s];
        __syncthreads();
        if (tid < NB) offs[tid + 1] += add;
        __syncthreads();
    }
    if (tid < NB) cur[tid] = offs[tid];
    __syncthreads();

    for (int j = tid; j < n; j += 1024) {
        float v0 = src[3 * j + 0];
        float v1 = src[3 * j + 1];
        float v2 = src[3 * j + 2];
        int ib = min(max((int)((v2 - ZMIN) * ZINV), 0), NB - 1);
        int r = atomicAdd(&cur[ib], 1);
        if (isX) {
            g_x[b][r] = make_float4(v0, v1, v2, __int_as_float(j));
        } else {
            int pb = (r >> 1) * 8 + (r & 1);
            float* yp = g_ypk[b];
            yp[pb + 0] = -2.0f * v0;
            yp[pb + 2] = -2.0f * v1;
            yp[pb + 4] = -2.0f * v2;
            yp[pb + 6] = v0 * v0 + v1 * v1 + v2 * v2;
        }
    }

    if (!isX) {
        if (tid < NB) g_yoff[b][tid] = offs[tid];
        if (tid == 0) g_yoff[b][NB] = offs[NB];
    }
}

// warp-uniform packed scan of candidate range [r0, e0) (rounded outward to
// whole pairs: superset-safe); per-lane min accumulated into (m0, m1)
__device__ __forceinline__ void scan_packed(const ulonglong2* __restrict__ Y2,
                                            int r0, int e0, int npairs,
                                            u64 X0, u64 X1, u64 X2,
                                            float& m0, float& m1)
{
    int plo = r0 >> 1;
    int phi = (e0 + 1) >> 1;
    if (phi > npairs) phi = npairs;
    int q = plo;
    for (; q + 1 < phi; q += 2) {
        ulonglong2 ua = Y2[2 * q],     va = Y2[2 * q + 1];
        ulonglong2 ub = Y2[2 * q + 2], vb = Y2[2 * q + 3];
        u64 ta = ffma2(X0, ua.x, ffma2(X1, ua.y, ffma2(X2, va.x, va.y)));
        u64 tb = ffma2(X0, ub.x, ffma2(X1, ub.y, ffma2(X2, vb.x, vb.y)));
        float al, ah, bl, bh;
        unpack2(ta, al, ah);
        unpack2(tb, bl, bh);
        m0 = fminf(m0, fminf(al, bl));
        m1 = fminf(m1, fminf(ah, bh));
    }
    if (q < phi) {
        ulonglong2 u = Y2[2 * q], v = Y2[2 * q + 1];
        u64 t = ffma2(X0, u.x, ffma2(X1, u.y, ffma2(X2, v.x, v.y)));
        float tl, th;
        unpack2(t, tl, th);
        m0 = fminf(m0, tl);
        m1 = fminf(m1, th);
    }
}

// ---------------- kernel 2: warp-window coherent search ----------------
extern "C" __global__ void __launch_bounds__(TS, 1)
search_kernel(float* __restrict__ out, int n, int nblk)
{
    __shared__ int   soff[NB + 1];
    __shared__ float buf[TS];
    __shared__ bool  amLast;

    const int tid  = threadIdx.x;
    const int w    = tid >> 5;
    const int lane = tid & 31;
    const int bx   = blockIdx.x;
    const int b    = blockIdx.y;

    for (int i = tid; i <= NB; i += TS) soff[i] = g_yoff[b][i];
    __syncthreads();

    // lane's sorted set1 point
    const int pos = (bx * (TS >> 5) + w) * 32 + lane;
    float4 X = g_x[b][pos];
    const float x0 = X.x, x1 = X.y, x2 = X.z;
    const int   orig = __float_as_int(X.w);
    const float sqx  = x0 * x0 + x1 * x1 + x2 * x2;
    const u64 X0 = bcast2(x0), X1 = bcast2(x1), X2 = bcast2(x2);

    int xb = min(max((int)((x2 - ZMIN) * ZINV), 0), NB - 1);

    // warp bucket span + warp z range
    int blo = xb, bhi = xb;
    float wzl = x2, wzh = x2;
    #pragma unroll
    for (int o = 16; o > 0; o >>= 1) {
        blo = min(blo, __shfl_xor_sync(0xffffffffu, blo, o));
        bhi = max(bhi, __shfl_xor_sync(0xffffffffu, bhi, o));
        wzl = fminf(wzl, __shfl_xor_sync(0xffffffffu, wzl, o));
        wzh = fmaxf(wzh, __shfl_xor_sync(0xffffffffu, wzh, o));
    }

    const ulonglong2* __restrict__ Y2 = (const ulonglong2*)g_ypk[b];
    const int npairs = n >> 1;

    // ---- phase A: joint scan of warp span +-1 bucket (expand if empty) ----
    int alo = max(blo - 1, 0), ahi = min(bhi + 1, NB - 1);
    for (;;) {
        if (soff[ahi + 1] > soff[alo]) break;
        bool grew = false;
        if (alo > 0)      { --alo; grew = true; }
        if (ahi < NB - 1) { ++ahi; grew = true; }
        if (!grew) break;
    }
    float m0 = 3.4e38f, m1 = 3.4e38f;
    scan_packed(Y2, soff[alo], soff[ahi + 1], npairs, X0, X1, X2, m0, m1);
    float bm = fminf(m0, m1);

    // per-lane upper bound, warp max -> window radius
    float ub = sqrtf(fmaxf(bm + sqx, 0.0f));
    float rr = ub;
    #pragma unroll
    for (int o = 16; o > 0; o >>= 1)
        rr = fmaxf(rr, __shfl_xor_sync(0xffffffffu, rr, o));

    // ---- phase B: warp window [wzl - rr, wzh + rr] ----
    int wlo = min(max((int)floorf((wzl - rr - ZMIN) * ZINV), 0), NB - 1);
    int whi = min(max((int)floorf((wzh + rr - ZMIN) * ZINV), 0), NB - 1);
    scan_packed(Y2, soff[wlo], soff[whi + 1], npairs, X0, X1, X2, m0, m1);

    float best = fminf(m0, m1);
    g_dist[b * n + orig] = sqrtf(fmaxf(best + sqx, 0.0f));

    __threadfence();
    __syncthreads();
    if (tid == 0) amLast = (atomicAdd(&g_count, 1) == nblk - 1);
    __syncthreads();

    if (amLast) {
        float s = 0.0f;
        const int total = NBATCH * n;
        for (int i = tid; i < total; i += TS) s += __ldcg(&g_dist[i]);
        buf[tid] = s;
        __syncthreads();
        #pragma unroll
        for (int st = TS / 2; st > 0; st >>= 1) {
            if (tid < st) buf[tid] += buf[tid + st];
            __syncthreads();
        }
        if (tid == 0) {
            out[0]  = buf[0];
            g_count = 0;           // self-reset for graph replay
        }
    }
}

extern "C" void kernel_launch(void* const* d_in, const int* in_sizes, int n_in,
                              void* d_out, int out_size)
{
    const float* set1 = (const float*)d_in[0];
    const float* set2 = (const float*)d_in[1];

    // in_sizes[0] = b * n * d = 2 * n * 3
    const int n = in_sizes[0] / (NBATCH * 3);
    const int sbx  = n / TS;              // search blocks per batch
    const int nblk = sbx * NBATCH;

    bucket_kernel<<<2 * NBATCH, 1024>>>(set1, set2, n);
    dim3 grid(sbx, NBATCH);
    search_kernel<<<grid, TS>>>((float*)d_out, n, nblk);
}